// round 13
// baseline (speedup 1.0000x reference)
#include <cuda_runtime.h>
#include <cstdint>

#define T_DIM 12
#define V_DIM 200
#define PADQ  17      // ulonglong2/float4 per padded band row (16 data + 1 pad)
#define PADW  68      // floats per padded band row
#define PADE  27      // floats per e_s row (25 data + 2 pad, odd stride)
#define NBLK  592u    // grid size = 148 SMs * 4 blocks (single wave, all resident)
#define NJOB  960u    // half-job quanta: 48 nt * 10 tile-pairs * 2 halves
#define JMOD  1552u   // NJOB + NBLK grabs consumed per launch (exactly)

typedef unsigned long long u64;

// Partial column sums: [nt(48)][band(4)][half(2)][w(200)] — every cell is
// written exactly once per launch (direct or transposed+zero-fill).
__device__ __align__(16) float g_psum[48 * 4 * 2 * 200];
// Monotone counters; never reset. Per launch: g_job += JMOD, g_ctr += NBLK.
__device__ unsigned g_job;
__device__ unsigned g_ctr;

// ---------------------------------------------------------------------------
__device__ __forceinline__ u64 padd2(u64 a, u64 b) {
    u64 r;
    asm("add.rn.f32x2 %0, %1, %2;" : "=l"(r) : "l"(a), "l"(b));
    return r;
}

__device__ __forceinline__ float2 unpack2(u64 v) {
    float2 r;
    asm("mov.b64 {%0, %1}, %2;" : "=f"(r.x), "=f"(r.y) : "l"(v));
    return r;
}

// ---------------------------------------------------------------------------
// Fused kernel: work-stealing compute + grid barrier + normalization.
//
// Quantum hj in [0,960): nt = hj/20, job = (hj%20)/2 -> band pair (i<=j),
// half = hj&1 -> v rows [25h, 25h+25) of band i, all 50 w of band j.
// exp(sum_f |y_v - y_w|) written to both permuted output locations
// (transpose staged in smem); column partials to g_psum slots by half.
// After the software grid barrier, block bid < 480 normalizes slab bid/10,
// chunk bid%10.
// ---------------------------------------------------------------------------
extern __shared__ unsigned char smem_raw[];

__global__ void __launch_bounds__(256, 4)
k_fused(const float* __restrict__ x, const float* __restrict__ a,
        float* __restrict__ out) {
    const int tid = threadIdx.x;

    float* ybj    = reinterpret_cast<float*>(smem_raw);   // [50*68] w-band
    float* ybi    = ybj + 50 * PADW;                       // [25*68] v-rows
    float* e_s    = ybi + 25 * PADW;                       // [50*27] transpose
    float* psum_s = e_s + 50 * PADE;                       // [250]
    unsigned* jslot = reinterpret_cast<unsigned*>(psum_s + 250);

    const float4* a4 = reinterpret_cast<const float4*>(a);
    const float4 ar = __ldg(&a4[tid & 15]);

    if (tid == 0) *jslot = atomicAdd(&g_job, 1u) % JMOD;
    __syncthreads();
    unsigned hj = *jslot;

    while (hj < NJOB) {
        if (tid == 0) *jslot = atomicAdd(&g_job, 1u) % JMOD;  // prefetch next

        const int nt  = (int)hj / 20;
        const int rem = (int)hj % 20;
        const int job = rem >> 1;
        const int h   = rem & 1;
        const int n   = nt / T_DIM;
        const int t   = nt % T_DIM;

        int i, j;
        if (job < 4)      { i = 0; j = job; }
        else if (job < 7) { i = 1; j = job - 3; }
        else if (job < 9) { i = 2; j = job - 5; }
        else              { i = 3; j = 3; }
        const bool diag = (i == j);

        const float4* x4 = reinterpret_cast<const float4*>(
            x + (size_t)nt * V_DIM * 64);

        // Load + pre-scale band j (w side, 50 rows). y = x*a valid: a >= 0.
        {
            float4* d = reinterpret_cast<float4*>(ybj);
            for (int idx = tid; idx < 800; idx += 256) {
                const int row = idx >> 4, fq = idx & 15;
                float4 v = x4[(j * 50 + row) * 16 + fq];
                v.x *= ar.x; v.y *= ar.y; v.z *= ar.z; v.w *= ar.w;
                d[row * PADQ + fq] = v;
            }
        }
        // Load v-rows (25) of band i (only when distinct from band j).
        if (!diag) {
            float4* d = reinterpret_cast<float4*>(ybi);
            for (int idx = tid; idx < 400; idx += 256) {
                const int row = idx >> 4, fq = idx & 15;
                float4 v = x4[(i * 50 + h * 25 + row) * 16 + fq];
                v.x *= ar.x; v.y *= ar.y; v.z *= ar.z; v.w *= ar.w;
                d[row * PADQ + fq] = v;
            }
        }
        __syncthreads();                       // sync#1
        const unsigned hj_next = *jslot;       // stable until next iter's write

        const float* ybv = diag ? (ybj + h * 25 * PADW) : ybi;
        const ulonglong2* yv2 = reinterpret_cast<const ulonglong2*>(ybv);
        const ulonglong2* yw2 = reinterpret_cast<const ulonglong2*>(ybj);

        const int wl = tid % 50;               // w column within band j
        const int vg = tid / 50;               // row group (0..4), vg==5 idle

        if (vg < 5) {
            const u64 NEG2 = 0x8000000080000000ULL;
            const u64 ABS2 = 0x7FFFFFFF7FFFFFFFULL;

            u64 rsum2[5];
            #pragma unroll
            for (int l = 0; l < 5; l++) rsum2[l] = 0ULL;

            const ulonglong2* ywbase = yw2 + wl * PADQ;
            const ulonglong2* yvb = yv2 + (size_t)(vg * 5) * PADQ;

            #pragma unroll 1
            for (int pass = 0; pass < 4; pass++) {
                u64 ywn[8];
                #pragma unroll
                for (int fq = 0; fq < 4; fq++) {
                    ulonglong2 r = ywbase[pass * 4 + fq];
                    ywn[2 * fq]     = r.x ^ NEG2;
                    ywn[2 * fq + 1] = r.y ^ NEG2;
                }
                const ulonglong2* rp = yvb + pass * 4;
                #pragma unroll
                for (int l = 0; l < 5; l++) {
                    u64 b0 = 0ULL, b1 = 0ULL, b2 = 0ULL, b3 = 0ULL;
                    #pragma unroll
                    for (int fq = 0; fq < 4; fq++) {
                        ulonglong2 q = rp[fq];             // broadcast LDS.128
                        u64 d0 = padd2(q.x, ywn[2 * fq])     & ABS2;
                        u64 d1 = padd2(q.y, ywn[2 * fq + 1]) & ABS2;
                        if (fq & 1) { b2 = padd2(b2, d0); b3 = padd2(b3, d1); }
                        else        { b0 = padd2(b0, d0); b1 = padd2(b1, d1); }
                    }
                    rsum2[l] = padd2(rsum2[l],
                                     padd2(padd2(b0, b1), padd2(b2, b3)));
                    rp += PADQ;
                }
            }

            // Epilogue: exp + direct stores + transpose staging + partials.
            float* opd = out + (((size_t)(i * T_DIM + t) * V_DIM)
                                + ((h * 25 + vg * 5) * 4 + n)) * V_DIM
                             + j * 50 + wl;
            float* esp = e_s + wl * PADE + vg * 5;
            float dsum = 0.0f;
            #pragma unroll
            for (int l = 0; l < 5; l++) {
                const float2 p = unpack2(rsum2[l]);
                const float e = __expf(p.x + p.y);
                opd[(size_t)l * 4 * V_DIM] = e;
                if (!diag) esp[l] = e;
                dsum += e;
            }
            psum_s[vg * 50 + wl] = dsum;
        }
        __syncthreads();                       // sync#2

        // Direct partials: slab i, w band j, slot h.
        if (tid < 50) {
            const float s = psum_s[tid] + psum_s[50 + tid] + psum_s[100 + tid]
                          + psum_s[150 + tid] + psum_s[200 + tid];
            g_psum[(((size_t)nt * 4 + i) * 2 + h) * V_DIM + j * 50 + tid] = s;
        }

        if (!diag) {
            // Transposed writes: slab j, row wl*4+n, col i*50 + 25h + cv.
            float* outj = out + ((size_t)(j * T_DIM + t) * V_DIM) * V_DIM;
            for (int k = tid; k < 1250; k += 256) {
                const int rw = k / 25, cv = k % 25;
                outj[(size_t)(rw * 4 + n) * V_DIM + i * 50 + h * 25 + cv] =
                    e_s[rw * PADE + cv];
            }
            // Transposed partials: slab j, w band i, slot h — real values on
            // this half's 25 w, zeros on the complement (slot sum = full).
            if (tid < 50) {
                float s = 0.0f;
                if ((tid / 25) == h) {
                    const int cv = tid - h * 25;
                    #pragma unroll
                    for (int rw = 0; rw < 50; rw++) s += e_s[rw * PADE + cv];
                }
                g_psum[(((size_t)nt * 4 + j) * 2 + h) * V_DIM + i * 50 + tid]
                    = s;
            }
        }
        hj = hj_next;
    }

    // ---- software grid barrier (592 blocks, all co-resident) ----
    __threadfence();
    __syncthreads();
    if (tid == 0) {
        atomicAdd(&g_ctr, 1u);
        volatile unsigned* p = &g_ctr;
        unsigned spins = 0;
        // Bounded: a logic bug degrades to wrong-answer, not a hang.
        while ((*p % NBLK) != 0u && spins < 20000000u) spins++;
    }
    __syncthreads();
    __threadfence();

    // ---- apply phase: block bid < 480 -> slab bid/10, chunk bid%10 ----
    const int bid = blockIdx.x;
    if (bid < 480) {
        float* sinv = reinterpret_cast<float*>(smem_raw);   // reuse smem
        const int ntp   = bid / 10;
        const int chunk = bid % 10;
        const int npp   = ntp / T_DIM;
        const int tt    = ntp % T_DIM;

        if (tid < 50) {
            const float4* p4 = reinterpret_cast<const float4*>(g_psum);
            float4 sa = make_float4(0.f, 0.f, 0.f, 0.f);
            #pragma unroll
            for (int nn = 0; nn < 4; nn++) {
                #pragma unroll
                for (int hh = 0; hh < 2; hh++) {
                    const float4 s =
                        p4[(((size_t)(nn * T_DIM + tt) * 4 + npp) * 2 + hh)
                           * 50 + tid];
                    sa.x += s.x; sa.y += s.y; sa.z += s.z; sa.w += s.w;
                }
            }
            float4 r;
            r.x = 1.0f / sa.x; r.y = 1.0f / sa.y;
            r.z = 1.0f / sa.z; r.w = 1.0f / sa.w;
            reinterpret_cast<float4*>(sinv)[tid] = r;
        }
        __syncthreads();

        const float4* si4 = reinterpret_cast<const float4*>(sinv);
        float4* o4 = reinterpret_cast<float4*>(out)
                     + (size_t)ntp * (V_DIM * V_DIM / 4)
                     + (size_t)chunk * 1000;

        #pragma unroll
        for (int jj = 0; jj < 4; jj++) {
            const int idx = tid + jj * 256;
            if (idx < 1000) {
                float4 v = o4[idx];
                const float4 m = si4[idx % 50];
                v.x *= m.x; v.y *= m.y; v.z *= m.z; v.w *= m.w;
                o4[idx] = v;
            }
        }
    }
}

// ---------------------------------------------------------------------------

extern "C" void kernel_launch(void* const* d_in, const int* in_sizes, int n_in,
                              void* d_out, int out_size) {
    const float* x = (const float*)d_in[0];
    const float* a = (const float*)d_in[1];
    // Defensive input-order check: a has exactly F=64 elements.
    if (n_in >= 2 && in_sizes[0] == 64) {
        x = (const float*)d_in[1];
        a = (const float*)d_in[0];
    }
    float* out = (float*)d_out;

    // Smem: band j + band i(25) + e_s + psum + jslot.
    const int smem_bytes =
        (50 * PADW + 25 * PADW + 50 * PADE + 250 + 4) * (int)sizeof(float);
    cudaFuncSetAttribute(k_fused, cudaFuncAttributeMaxDynamicSharedMemorySize,
                         smem_bytes);

    k_fused<<<NBLK, 256, smem_bytes>>>(x, a, out);
}